// round 5
// baseline (speedup 1.0000x reference)
#include <cuda_runtime.h>
#include <cuda_bf16.h>
#include <cstdint>

#define NN   50000
#define F_IN 256
#define HID  128
#define NH   8
#define EE   800000
#define MM   3
#define OUTD 8
#define GBM  128
#define GBK  16
#define SEGS (MM * NN)

// ---------------- scratch (device globals; no allocation) ----------------
__device__ float d_h [NN * HID];
__device__ float d_fs[(size_t)MM * NN * HID];
__device__ float d_el[(size_t)MM * NN * NH];
__device__ float d_er[(size_t)MM * NN * NH];
__device__ float d_vd[MM * NH * HID];
__device__ float d_z [(size_t)NN * MM * HID];
__device__ float d_w [NN * MM];
__device__ int   d_cnt [SEGS];
__device__ int   d_off [SEGS];
__device__ int   d_pos [SEGS];
__device__ int   d_ssrc[MM * EE];

__device__ __forceinline__ void ffma2(unsigned long long &d,
                                      unsigned long long a,
                                      unsigned long long b)
{
    asm("fma.rn.f32x2 %0, %1, %2, %3;" : "=l"(d) : "l"(a), "l"(b), "l"(d));
}

__device__ __forceinline__ float elu1(float v)
{
    return v > 0.f ? v : (__expf(v) - 1.f);
}

// ---------------- f32x2 SGEMM, 128 out cols, 128-row tiles, double-buffered -
// mode 0: C = A@B + bias                       (fc layer)
// mode 1: batched over grid.y = m: C = A@B ; fused el = head-dot with att
// mode 2: semantic: A' = elu(A); p = tanh(A'@B + bias) . w2 -> wout (no C)
__global__ void __launch_bounds__(256, 2) gemm2(
    const float* __restrict__ A, const float* __restrict__ Bw,
    const float* __restrict__ bias, float* __restrict__ Cb,
    const float* __restrict__ att, float* __restrict__ elb,
    const float* __restrict__ w2, float* __restrict__ wout,
    int Mrows, int K, int mode)
{
    __shared__ __align__(16) float2 As2[2][GBK][GBM];  // 32 KB (duplicated A)
    __shared__ __align__(16) float  Bs [2][GBK][HID];  // 16 KB

    const int tid = threadIdx.x;
    const int tx = tid & 15;          // col group: cols tx*8 .. tx*8+7
    const int ty = tid >> 4;          // row group: rows ty*8 .. ty*8+7
    const int rowBase = blockIdx.x * GBM;

    const float* B = Bw; float* C = Cb; const float* av = nullptr; float* eo = nullptr;
    if (mode == 1) {
        int m = blockIdx.y;
        B  = Bw  + (size_t)m * HID * HID;
        C  = Cb  + (size_t)m * NN * HID;
        av = att + (size_t)m * HID;
        eo = elb + (size_t)m * NN * NH;
    }

    // loader thread mapping
    const int arow = tid >> 1;            // 0..127
    const int ac   = (tid & 1) * 8;       // 0 or 8
    const int brow = tid >> 4;            // 0..15
    const int bc   = (tid & 15) * 8;      // 0..120
    const int grA  = rowBase + arow;
    const bool aok = grA < Mrows;
    const float* Aor = A + (size_t)grA * K;

    unsigned long long acc[8][4];
#pragma unroll
    for (int i = 0; i < 8; i++)
#pragma unroll
        for (int j = 0; j < 4; j++) acc[i][j] = 0ull;

    float4 aR0, aR1, bR0, bR1;

    // prologue: load tile 0
    aR0 = aok ? *reinterpret_cast<const float4*>(Aor + ac)     : make_float4(0.f,0.f,0.f,0.f);
    aR1 = aok ? *reinterpret_cast<const float4*>(Aor + ac + 4) : make_float4(0.f,0.f,0.f,0.f);
    bR0 = *reinterpret_cast<const float4*>(B + (size_t)brow * HID + bc);
    bR1 = *reinterpret_cast<const float4*>(B + (size_t)brow * HID + bc + 4);

    int p = 0;
    // store tile 0
    {
        float4 a0 = aR0, a1 = aR1;
        if (mode == 2) {
            a0.x = elu1(a0.x); a0.y = elu1(a0.y); a0.z = elu1(a0.z); a0.w = elu1(a0.w);
            a1.x = elu1(a1.x); a1.y = elu1(a1.y); a1.z = elu1(a1.z); a1.w = elu1(a1.w);
        }
        As2[p][ac + 0][arow] = make_float2(a0.x, a0.x);
        As2[p][ac + 1][arow] = make_float2(a0.y, a0.y);
        As2[p][ac + 2][arow] = make_float2(a0.z, a0.z);
        As2[p][ac + 3][arow] = make_float2(a0.w, a0.w);
        As2[p][ac + 4][arow] = make_float2(a1.x, a1.x);
        As2[p][ac + 5][arow] = make_float2(a1.y, a1.y);
        As2[p][ac + 6][arow] = make_float2(a1.z, a1.z);
        As2[p][ac + 7][arow] = make_float2(a1.w, a1.w);
        *reinterpret_cast<float4*>(&Bs[p][brow][bc])     = bR0;
        *reinterpret_cast<float4*>(&Bs[p][brow][bc + 4]) = bR1;
    }
    __syncthreads();

    for (int k0 = GBK; k0 <= K; k0 += GBK) {
        // prefetch next tile into regs (if any)
        if (k0 < K) {
            aR0 = aok ? *reinterpret_cast<const float4*>(Aor + k0 + ac)     : make_float4(0.f,0.f,0.f,0.f);
            aR1 = aok ? *reinterpret_cast<const float4*>(Aor + k0 + ac + 4) : make_float4(0.f,0.f,0.f,0.f);
            bR0 = *reinterpret_cast<const float4*>(B + (size_t)(k0 + brow) * HID + bc);
            bR1 = *reinterpret_cast<const float4*>(B + (size_t)(k0 + brow) * HID + bc + 4);
        }

        // compute over buffer p
#pragma unroll
        for (int kk = 0; kk < GBK; kk++) {
            ulonglong2 a01 = *reinterpret_cast<const ulonglong2*>(&As2[p][kk][ty * 8]);
            ulonglong2 a23 = *reinterpret_cast<const ulonglong2*>(&As2[p][kk][ty * 8 + 2]);
            ulonglong2 a45 = *reinterpret_cast<const ulonglong2*>(&As2[p][kk][ty * 8 + 4]);
            ulonglong2 a67 = *reinterpret_cast<const ulonglong2*>(&As2[p][kk][ty * 8 + 6]);
            ulonglong2 b01 = *reinterpret_cast<const ulonglong2*>(&Bs[p][kk][tx * 8]);
            ulonglong2 b23 = *reinterpret_cast<const ulonglong2*>(&Bs[p][kk][tx * 8 + 4]);
            unsigned long long ar[8] = {a01.x, a01.y, a23.x, a23.y, a45.x, a45.y, a67.x, a67.y};
            unsigned long long br[4] = {b01.x, b01.y, b23.x, b23.y};
#pragma unroll
            for (int i = 0; i < 8; i++) {
                ffma2(acc[i][0], ar[i], br[0]);
                ffma2(acc[i][1], ar[i], br[1]);
                ffma2(acc[i][2], ar[i], br[2]);
                ffma2(acc[i][3], ar[i], br[3]);
            }
        }

        // store prefetched tile into other buffer
        if (k0 < K) {
            int q = p ^ 1;
            float4 a0 = aR0, a1 = aR1;
            if (mode == 2) {
                a0.x = elu1(a0.x); a0.y = elu1(a0.y); a0.z = elu1(a0.z); a0.w = elu1(a0.w);
                a1.x = elu1(a1.x); a1.y = elu1(a1.y); a1.z = elu1(a1.z); a1.w = elu1(a1.w);
            }
            As2[q][ac + 0][arow] = make_float2(a0.x, a0.x);
            As2[q][ac + 1][arow] = make_float2(a0.y, a0.y);
            As2[q][ac + 2][arow] = make_float2(a0.z, a0.z);
            As2[q][ac + 3][arow] = make_float2(a0.w, a0.w);
            As2[q][ac + 4][arow] = make_float2(a1.x, a1.x);
            As2[q][ac + 5][arow] = make_float2(a1.y, a1.y);
            As2[q][ac + 6][arow] = make_float2(a1.z, a1.z);
            As2[q][ac + 7][arow] = make_float2(a1.w, a1.w);
            *reinterpret_cast<float4*>(&Bs[q][brow][bc])     = bR0;
            *reinterpret_cast<float4*>(&Bs[q][brow][bc + 4]) = bR1;
            __syncthreads();
            p = q;
        }
    }

    // unpack accumulators
    float c[8][8];
#pragma unroll
    for (int i = 0; i < 8; i++)
#pragma unroll
        for (int j = 0; j < 4; j++) {
            float2 v = *reinterpret_cast<float2*>(&acc[i][j]);
            c[i][2 * j]     = v.x;
            c[i][2 * j + 1] = v.y;
        }

    const int r0 = rowBase + ty * 8;

    if (mode == 0) {
#pragma unroll
        for (int i = 0; i < 8; i++) {
            int r = r0 + i;
            if (r >= Mrows) break;
#pragma unroll
            for (int j = 0; j < 8; j++) c[i][j] += bias[tx * 8 + j];
            *reinterpret_cast<float4*>(C + (size_t)r * HID + tx * 8)     = make_float4(c[i][0], c[i][1], c[i][2], c[i][3]);
            *reinterpret_cast<float4*>(C + (size_t)r * HID + tx * 8 + 4) = make_float4(c[i][4], c[i][5], c[i][6], c[i][7]);
        }
    } else if (mode == 1) {
        float4 av0 = *reinterpret_cast<const float4*>(av + tx * 8);
        float4 av1 = *reinterpret_cast<const float4*>(av + tx * 8 + 4);
        float avv[8] = {av0.x, av0.y, av0.z, av0.w, av1.x, av1.y, av1.z, av1.w};
        int h = tx >> 1;
#pragma unroll
        for (int i = 0; i < 8; i++) {
            int r = r0 + i;
            bool ok = r < Mrows;
            if (ok) {
                *reinterpret_cast<float4*>(C + (size_t)r * HID + tx * 8)     = make_float4(c[i][0], c[i][1], c[i][2], c[i][3]);
                *reinterpret_cast<float4*>(C + (size_t)r * HID + tx * 8 + 4) = make_float4(c[i][4], c[i][5], c[i][6], c[i][7]);
            }
            float pdot = 0.f;
#pragma unroll
            for (int j = 0; j < 8; j++) pdot += c[i][j] * avv[j];
            pdot += __shfl_xor_sync(0xffffffffu, pdot, 1);
            if (ok && !(tx & 1)) eo[(size_t)r * NH + h] = pdot;
        }
    } else {
        float bloc[8], wloc[8];
#pragma unroll
        for (int j = 0; j < 8; j++) { bloc[j] = bias[tx * 8 + j]; wloc[j] = w2[tx * 8 + j]; }
#pragma unroll
        for (int i = 0; i < 8; i++) {
            int r = r0 + i;
            float pdot = 0.f;
#pragma unroll
            for (int j = 0; j < 8; j++) pdot += tanhf(c[i][j] + bloc[j]) * wloc[j];
            pdot += __shfl_xor_sync(0xffffffffu, pdot, 1);
            pdot += __shfl_xor_sync(0xffffffffu, pdot, 2);
            pdot += __shfl_xor_sync(0xffffffffu, pdot, 4);
            pdot += __shfl_xor_sync(0xffffffffu, pdot, 8);
            if (tx == 0 && r < Mrows) wout[r] = pdot;
        }
    }
}

// ---------------- Vdst[m][h][k] = sum_d Wdst[m][k][h*16+d] * ar[m][h][d] ----
__global__ void vdst_kernel(const float* __restrict__ Wdst, const float* __restrict__ ar,
                            float* __restrict__ vd)
{
    int t = blockIdx.x * blockDim.x + threadIdx.x;
    if (t >= MM * NH * HID) return;
    int m = t / (NH * HID);
    int r = t - m * (NH * HID);
    int h = r / HID;
    int k = r - h * HID;
    const float* W = Wdst + ((size_t)m * HID + k) * HID + h * 16;
    const float* a = ar + (m * NH + h) * 16;
    float s = 0.f;
#pragma unroll
    for (int d = 0; d < 16; d++) s += W[d] * a[d];
    vd[(m * NH + h) * HID + k] = s;
}

// ---------------- er[m][n][h] = h_[n,:] . Vdst[m][h][:] ---------------------
// ONE WARP PER NODE (grid must supply NN warps)
__global__ void er_kernel(const float* __restrict__ hfeat, const float* __restrict__ vd,
                          float* __restrict__ er)
{
    __shared__ float sV[MM * NH * HID];
    for (int i = threadIdx.x; i < MM * NH * HID; i += blockDim.x) sV[i] = vd[i];
    __syncthreads();
    int warp = (blockIdx.x * blockDim.x + threadIdx.x) >> 5;
    int lane = threadIdx.x & 31;
    if (warp >= NN) return;
    float4 hv = *reinterpret_cast<const float4*>(hfeat + (size_t)warp * HID + lane * 4);
#pragma unroll
    for (int m = 0; m < MM; m++) {
#pragma unroll
        for (int hh = 0; hh < NH; hh++) {
            float4 vv = *reinterpret_cast<const float4*>(&sV[(m * NH + hh) * HID + lane * 4]);
            float p = hv.x * vv.x + hv.y * vv.y + hv.z * vv.z + hv.w * vv.w;
            p += __shfl_xor_sync(0xffffffffu, p, 16);
            p += __shfl_xor_sync(0xffffffffu, p, 8);
            p += __shfl_xor_sync(0xffffffffu, p, 4);
            p += __shfl_xor_sync(0xffffffffu, p, 2);
            p += __shfl_xor_sync(0xffffffffu, p, 1);
            if (lane == 0) er[((size_t)m * NN + warp) * NH + hh] = p;
        }
    }
}

// ---------------- CSR build: count / scan / fill ----------------------------
__global__ void count_kernel(const int* __restrict__ dst, int* __restrict__ cnt)
{
    int t = blockIdx.x * blockDim.x + threadIdx.x;
    if (t >= MM * EE) return;
    int m = t / EE;
    atomicAdd(&cnt[m * NN + dst[t]], 1);
}

#define SCAN_T 1024
#define SCAN_CH ((SEGS + SCAN_T - 1) / SCAN_T)
__global__ void __launch_bounds__(SCAN_T) scan_kernel(const int* __restrict__ cnt,
                                                      int* __restrict__ off,
                                                      int* __restrict__ pos)
{
    __shared__ int sm[SCAN_T];
    int tid = threadIdx.x;
    int base = tid * SCAN_CH;
    int s = 0;
    for (int i = 0; i < SCAN_CH; i++) {
        int idx = base + i;
        if (idx < SEGS) s += cnt[idx];
    }
    sm[tid] = s;
    __syncthreads();
    for (int d = 1; d < SCAN_T; d <<= 1) {
        int v = (tid >= d) ? sm[tid - d] : 0;
        __syncthreads();
        sm[tid] += v;
        __syncthreads();
    }
    int run = sm[tid] - s;  // exclusive prefix of this chunk
    for (int i = 0; i < SCAN_CH; i++) {
        int idx = base + i;
        if (idx < SEGS) {
            off[idx] = run;
            pos[idx] = run;
            run += cnt[idx];
        }
    }
}

__global__ void fill_kernel(const int* __restrict__ src, const int* __restrict__ dst,
                            int* __restrict__ pos, int* __restrict__ ssrc)
{
    int t = blockIdx.x * blockDim.x + threadIdx.x;
    if (t >= MM * EE) return;
    int m = t / EE;
    int p = atomicAdd(&pos[m * NN + dst[t]], 1);
    ssrc[p] = src[t];
}

// ---------------- gather: per (m, dst) warp: softmax + weighted aggregation -
__global__ void gather_kernel(const int* __restrict__ ssrc,
                              const int* __restrict__ off, const int* __restrict__ cnt,
                              const float* __restrict__ el, const float* __restrict__ er,
                              const float* __restrict__ fs, float* __restrict__ z)
{
    int gw = (blockIdx.x * blockDim.x + threadIdx.x) >> 5;
    int lane = threadIdx.x & 31;
    if (gw >= SEGS) return;
    int m = gw / NN;
    int n = gw - m * NN;
    int beg = off[gw];
    int num = cnt[gw];
    const float* elm = el + (size_t)m * NN * NH;
    const float* fsm = fs + (size_t)m * NN * HID;

    // pass 1: per-head exp-sum (no max shift; softmax is shift-invariant and
    // logits are O(1) with these weight scales)
    int h8 = lane & 7;
    float er8 = er[(size_t)gw * NH + h8];
    float ssum = 0.f;
    for (int it = (lane >> 3); it < num; it += 4) {
        int s = ssrc[beg + it];
        float v = elm[s * NH + h8] + er8;
        v = v > 0.f ? v : 0.2f * v;
        ssum += __expf(v);
    }
    ssum += __shfl_xor_sync(0xffffffffu, ssum, 8);
    ssum += __shfl_xor_sync(0xffffffffu, ssum, 16);
    // lane i<8 now holds head-i sum; remap to pass-2 head = lane>>2
    int h4 = lane >> 2;
    float ssum4 = __shfl_sync(0xffffffffu, ssum, h4);
    float er4   = __shfl_sync(0xffffffffu, er8, h4);
    float inv = 1.f / fmaxf(ssum4, 1e-9f);

    // pass 2: accumulate fs[src] * alpha into registers (no atomics)
    float4 acc = make_float4(0.f, 0.f, 0.f, 0.f);
    int s = (num > 0) ? ssrc[beg] : 0;
    for (int it = 0; it < num; ++it) {
        int snext = (it + 1 < num) ? ssrc[beg + it + 1] : 0;
        float v = elm[s * NH + h4] + er4;
        float4 f = *reinterpret_cast<const float4*>(fsm + (size_t)s * HID + lane * 4);
        v = v > 0.f ? v : 0.2f * v;
        float a = __expf(v) * inv;
        acc.x += f.x * a; acc.y += f.y * a; acc.z += f.z * a; acc.w += f.w * a;
        s = snext;
    }
    *reinterpret_cast<float4*>(z + ((size_t)n * MM + m) * HID + lane * 4) = acc;
}

// ---------------- final: beta softmax over w, elu(z) fuse, output GEMV ------
__global__ void final_kernel(const float* __restrict__ w, const float* __restrict__ z,
                             const float* __restrict__ Wout, const float* __restrict__ bout,
                             float* __restrict__ out)
{
    __shared__ float sW[HID * OUTD];
    for (int i = threadIdx.x; i < HID * OUTD; i += blockDim.x) sW[i] = Wout[i];
    __syncthreads();
    int warp = (blockIdx.x * blockDim.x + threadIdx.x) >> 5;
    int lane = threadIdx.x & 31;
    if (warp >= NN) return;
    float w0 = w[warp * 3 + 0], w1 = w[warp * 3 + 1], w2 = w[warp * 3 + 2];
    float mx = fmaxf(w0, fmaxf(w1, w2));
    float e0 = __expf(w0 - mx), e1 = __expf(w1 - mx), e2 = __expf(w2 - mx);
    float inv = 1.f / (e0 + e1 + e2);
    float b0 = e0 * inv, b1 = e1 * inv, b2 = e2 * inv;
    const float* zr = z + (size_t)warp * (MM * HID);
    float4 z0 = *reinterpret_cast<const float4*>(zr + lane * 4);
    float4 z1 = *reinterpret_cast<const float4*>(zr + HID + lane * 4);
    float4 z2 = *reinterpret_cast<const float4*>(zr + 2 * HID + lane * 4);
    float f[4];
    f[0] = b0 * elu1(z0.x) + b1 * elu1(z1.x) + b2 * elu1(z2.x);
    f[1] = b0 * elu1(z0.y) + b1 * elu1(z1.y) + b2 * elu1(z2.y);
    f[2] = b0 * elu1(z0.z) + b1 * elu1(z1.z) + b2 * elu1(z2.z);
    f[3] = b0 * elu1(z0.w) + b1 * elu1(z1.w) + b2 * elu1(z2.w);
    float po[OUTD];
#pragma unroll
    for (int o = 0; o < OUTD; o++) {
        po[o] = 0.f;
#pragma unroll
        for (int j = 0; j < 4; j++)
            po[o] += f[j] * sW[(lane * 4 + j) * OUTD + o];
    }
#pragma unroll
    for (int off = 16; off; off >>= 1)
#pragma unroll
        for (int o = 0; o < OUTD; o++)
            po[o] += __shfl_down_sync(0xffffffffu, po[o], off);
    if (lane == 0)
#pragma unroll
        for (int o = 0; o < OUTD; o++)
            out[(size_t)warp * OUTD + o] = po[o] + bout[o];
}

// ---------------- launch ----------------------------------------------------
extern "C" void kernel_launch(void* const* d_in, const int* in_sizes, int n_in,
                              void* d_out, int out_size)
{
    const float* features = (const float*)d_in[0];
    const float* W_fc     = (const float*)d_in[1];
    const float* b_fc     = (const float*)d_in[2];
    const float* W_src    = (const float*)d_in[3];
    const float* W_dst    = (const float*)d_in[4];
    const float* attn_l   = (const float*)d_in[5];
    const float* attn_r   = (const float*)d_in[6];
    const float* W_sem1   = (const float*)d_in[7];
    const float* b_sem1   = (const float*)d_in[8];
    const float* w_sem2   = (const float*)d_in[9];
    const float* W_out    = (const float*)d_in[10];
    const float* b_out    = (const float*)d_in[11];
    const int*   src_idx  = (const int*)d_in[12];
    const int*   dst_idx  = (const int*)d_in[13];
    float* out = (float*)d_out;

    float *h, *fs, *el, *er, *vd, *z, *w;
    int *cnt, *off, *pos, *ssrc;
    cudaGetSymbolAddress((void**)&h,   d_h);
    cudaGetSymbolAddress((void**)&fs,  d_fs);
    cudaGetSymbolAddress((void**)&el,  d_el);
    cudaGetSymbolAddress((void**)&er,  d_er);
    cudaGetSymbolAddress((void**)&vd,  d_vd);
    cudaGetSymbolAddress((void**)&z,   d_z);
    cudaGetSymbolAddress((void**)&w,   d_w);
    cudaGetSymbolAddress((void**)&cnt, d_cnt);
    cudaGetSymbolAddress((void**)&off, d_off);
    cudaGetSymbolAddress((void**)&pos, d_pos);
    cudaGetSymbolAddress((void**)&ssrc,d_ssrc);

    cudaMemsetAsync(cnt, 0, SEGS * sizeof(int));

    const int MT = (NN + GBM - 1) / GBM;

    // CSR build (independent of GEMMs)
    count_kernel<<<(MM * EE + 255) / 256, 256>>>(dst_idx, cnt);
    scan_kernel<<<1, SCAN_T>>>(cnt, off, pos);
    fill_kernel<<<(MM * EE + 255) / 256, 256>>>(src_idx, dst_idx, pos, ssrc);

    // h = features @ W_fc + b_fc
    gemm2<<<dim3(MT, 1), 256>>>(features, W_fc, b_fc, h, nullptr, nullptr,
                                nullptr, nullptr, NN, F_IN, 0);

    // fs[m] = h @ W_src[m] with fused el; er via factored Vdst
    vdst_kernel<<<(MM * NH * HID + 255) / 256, 256>>>(W_dst, attn_r, vd);
    gemm2<<<dim3(MT, MM), 256>>>(h, W_src, nullptr, fs, attn_l, el,
                                 nullptr, nullptr, NN, HID, 1);
    er_kernel<<<(NN + 7) / 8, 256>>>(h, vd, er);

    // edge softmax + aggregation, atomic-free
    gather_kernel<<<(SEGS + 7) / 8, 256>>>(ssrc, off, cnt, el, er, fs, z);

    // semantic attention: w = tanh(elu(z) @ W_sem1 + b_sem1) . w_sem2
    gemm2<<<dim3((NN * MM + GBM - 1) / GBM, 1), 256>>>(z, W_sem1, b_sem1, nullptr,
                                nullptr, nullptr, w_sem2, w, NN * MM, HID, 2);

    final_kernel<<<(NN + 7) / 8, 256>>>(w, z, W_out, b_out, out);
}

// round 7
// speedup vs baseline: 1.5820x; 1.5820x over previous
#include <cuda_runtime.h>
#include <cuda_bf16.h>
#include <cstdint>

#define NN   50000
#define F_IN 256
#define HID  128
#define NH   8
#define EE   800000
#define MM   3
#define OUTD 8
#define SEGS (MM * NN)
#define BKE  64
#define STR  72   // padded smem row stride (halves)

// ---------------- scratch (device globals; no allocation) ----------------
__device__ float d_h [NN * HID];
__device__ float d_fs[(size_t)MM * NN * HID];
__device__ float d_el[(size_t)MM * NN * NH];
__device__ float d_er[(size_t)MM * NN * NH];
__device__ float d_vd[MM * NH * HID];
__device__ float d_z [(size_t)NN * MM * HID];
__device__ float d_w [NN * MM];
__device__ int   d_cnt [SEGS];
__device__ int   d_off [SEGS];
__device__ int   d_pos [SEGS];
__device__ int   d_ssrc[MM * EE];
// B' = [Bhi ; Blo ; Bhi] transposed weights, [128][3K] row-major bf16
__device__ __nv_bfloat16 d_Bfc[128 * 3 * F_IN];
__device__ __nv_bfloat16 d_Bpr[MM * 128 * 3 * HID];
__device__ __nv_bfloat16 d_Bsm[128 * 3 * HID];

__device__ __forceinline__ float elu1(float v)
{
    return v > 0.f ? v : (__expf(v) - 1.f);
}

__device__ __forceinline__ uint32_t smem_u32(const void* p) {
    uint32_t a;
    asm("{ .reg .u64 t; cvta.to.shared.u64 t, %1; cvt.u32.u64 %0, t; }"
        : "=r"(a) : "l"(p));
    return a;
}

// ---------------- weight prep: B'[n][keff] = split-transposed W -------------
// W: [K,128] row-major.  B'[n][0..K)=hi, [K..2K)=lo, [2K..3K)=hi
__global__ void prep_b(const float* __restrict__ W, __nv_bfloat16* __restrict__ Bp, int K)
{
    int t = blockIdx.x * blockDim.x + threadIdx.x;
    if (t >= 128 * K) return;
    int k = t >> 7;
    int n = t & 127;
    float v = W[(size_t)k * 128 + n];
    __nv_bfloat16 h = __float2bfloat16(v);
    __nv_bfloat16 l = __float2bfloat16(v - __bfloat162float(h));
    size_t base = (size_t)n * 3 * K;
    Bp[base + k]         = h;
    Bp[base + K + k]     = l;
    Bp[base + 2 * K + k] = h;
}

// ---------------- tensor-core GEMM via mma.sync bf16 hi/lo ------------------
// tile 128x128, 8 warps (2x4), K-chunks of 64 over Keff=3K
// mode 0: C = A@W + bias     mode 1 (grid.y=m): C = A@W ; el head-dots fused
// mode 2: A'=elu(A); wout = tanh(A'@W + bias) . w2  (no C store)
__global__ void __launch_bounds__(256) mgemm(
    const float* __restrict__ A, const __nv_bfloat16* __restrict__ Bp,
    const float* __restrict__ bias, float* __restrict__ Cb,
    const float* __restrict__ att, float* __restrict__ elb,
    const float* __restrict__ w2, float* __restrict__ wout,
    int Mrows, int K, int mode)
{
    __shared__ __nv_bfloat16 As[128 * STR];
    __shared__ __nv_bfloat16 Bs[128 * STR];
    __shared__ float redbuf[128];

    const int tid = threadIdx.x;
    const int lane = tid & 31;
    const int wid = tid >> 5;
    const int warp_m = wid >> 2;      // 0..1 -> rows warp_m*64
    const int warp_n = wid & 3;       // 0..3 -> cols warp_n*32
    const int rowBase = blockIdx.x * 128;
    const int Keff = 3 * K;

    const __nv_bfloat16* B = Bp;
    float* C = Cb; const float* av = att; float* eo = elb;
    if (mode == 1) {
        int m = blockIdx.y;
        B  += (size_t)m * 128 * Keff;
        C  += (size_t)m * NN * HID;
        av += (size_t)m * HID;
        eo += (size_t)m * NN * NH;
    }

    float cfr[4][4][4];
#pragma unroll
    for (int mt = 0; mt < 4; mt++)
#pragma unroll
        for (int nt = 0; nt < 4; nt++)
#pragma unroll
            for (int q = 0; q < 4; q++) cfr[mt][nt][q] = 0.f;

    // loader mapping: thread -> (row, half-of-64-col-chunk)
    const int lrow = tid >> 1;
    const int lcol = (tid & 1) * 32;
    const bool aok = (rowBase + lrow) < Mrows;
    const float* Arow = A + (size_t)(rowBase + lrow) * K;

    const uint32_t asb = smem_u32(As);
    const uint32_t bsb = smem_u32(Bs);

    for (int kc = 0; kc < Keff; kc += BKE) {
        int region = kc / K;
        int ksrc = kc - region * K;
        bool lo_a = (region == 2);

        // ---- load A chunk (fp32 -> bf16 hi or lo) ----
        {
            uint32_t* dst = reinterpret_cast<uint32_t*>(&As[lrow * STR + lcol]);
#pragma unroll
            for (int q = 0; q < 8; q++) {
                float4 v = aok ? *reinterpret_cast<const float4*>(Arow + ksrc + lcol + q * 4)
                               : make_float4(0.f, 0.f, 0.f, 0.f);
                if (mode == 2) { v.x = elu1(v.x); v.y = elu1(v.y); v.z = elu1(v.z); v.w = elu1(v.w); }
                __nv_bfloat16 e0 = __float2bfloat16(v.x);
                __nv_bfloat16 e1 = __float2bfloat16(v.y);
                __nv_bfloat16 e2 = __float2bfloat16(v.z);
                __nv_bfloat16 e3 = __float2bfloat16(v.w);
                if (lo_a) {
                    e0 = __float2bfloat16(v.x - __bfloat162float(e0));
                    e1 = __float2bfloat16(v.y - __bfloat162float(e1));
                    e2 = __float2bfloat16(v.z - __bfloat162float(e2));
                    e3 = __float2bfloat16(v.w - __bfloat162float(e3));
                }
                __nv_bfloat162 p0 = __halves2bfloat162(e0, e1);
                __nv_bfloat162 p1 = __halves2bfloat162(e2, e3);
                dst[q * 2]     = *reinterpret_cast<uint32_t*>(&p0);
                dst[q * 2 + 1] = *reinterpret_cast<uint32_t*>(&p1);
            }
        }
        // ---- load B chunk (pre-split bf16, straight copy) ----
        {
            const uint4* g = reinterpret_cast<const uint4*>(B + (size_t)lrow * Keff + kc + lcol);
            uint4* dst = reinterpret_cast<uint4*>(&Bs[lrow * STR + lcol]);
#pragma unroll
            for (int q = 0; q < 4; q++) dst[q] = g[q];
        }
        __syncthreads();

        // ---- 4 k-steps of 16 ----
#pragma unroll
        for (int ks = 0; ks < 4; ks++) {
            int k0 = ks * 16;
            uint32_t afr[4][4];
#pragma unroll
            for (int mt = 0; mt < 4; mt++) {
                int r = warp_m * 64 + mt * 16 + (lane & 15);
                int kk = k0 + (lane >> 4) * 8;
                uint32_t addr = asb + (uint32_t)(r * STR + kk) * 2u;
                asm volatile("ldmatrix.sync.aligned.m8n8.x4.shared.b16 {%0,%1,%2,%3}, [%4];"
                             : "=r"(afr[mt][0]), "=r"(afr[mt][1]), "=r"(afr[mt][2]), "=r"(afr[mt][3])
                             : "r"(addr));
            }
            uint32_t bfr[4][2];
#pragma unroll
            for (int nt = 0; nt < 4; nt++) {
                int n = warp_n * 32 + nt * 8 + (lane & 7);
                int kk = k0 + ((lane >> 3) & 1) * 8;
                uint32_t addr = bsb + (uint32_t)(n * STR + kk) * 2u;
                asm volatile("ldmatrix.sync.aligned.m8n8.x2.shared.b16 {%0,%1}, [%2];"
                             : "=r"(bfr[nt][0]), "=r"(bfr[nt][1])
                             : "r"(addr));
            }
#pragma unroll
            for (int mt = 0; mt < 4; mt++)
#pragma unroll
                for (int nt = 0; nt < 4; nt++) {
                    asm volatile(
                        "mma.sync.aligned.m16n8k16.row.col.f32.bf16.bf16.f32 "
                        "{%0,%1,%2,%3}, {%4,%5,%6,%7}, {%8,%9}, {%0,%1,%2,%3};"
                        : "+f"(cfr[mt][nt][0]), "+f"(cfr[mt][nt][1]),
                          "+f"(cfr[mt][nt][2]), "+f"(cfr[mt][nt][3])
                        : "r"(afr[mt][0]), "r"(afr[mt][1]), "r"(afr[mt][2]), "r"(afr[mt][3]),
                          "r"(bfr[nt][0]), "r"(bfr[nt][1]));
                }
        }
        __syncthreads();
    }

    // ---- epilogues ----
    const int g = lane >> 2, j = lane & 3;

    if (mode == 0 || mode == 1) {
#pragma unroll
        for (int mt = 0; mt < 4; mt++) {
            int r1 = rowBase + warp_m * 64 + mt * 16 + g;
            int r2 = r1 + 8;
#pragma unroll
            for (int nt = 0; nt < 4; nt++) {
                int c = warp_n * 32 + nt * 8 + j * 2;
                float b0 = 0.f, b1 = 0.f;
                if (mode == 0) { b0 = bias[c]; b1 = bias[c + 1]; }
                if (r1 < Mrows)
                    *reinterpret_cast<float2*>(C + (size_t)r1 * HID + c) =
                        make_float2(cfr[mt][nt][0] + b0, cfr[mt][nt][1] + b1);
                if (r2 < Mrows)
                    *reinterpret_cast<float2*>(C + (size_t)r2 * HID + c) =
                        make_float2(cfr[mt][nt][2] + b0, cfr[mt][nt][3] + b1);
            }
            if (mode == 1) {
                float p1[2] = {0.f, 0.f}, p2[2] = {0.f, 0.f};
#pragma unroll
                for (int nt = 0; nt < 4; nt++) {
                    int hl = nt >> 1;
                    int c = warp_n * 32 + nt * 8 + j * 2;
                    float a0 = av[c], a1 = av[c + 1];
                    p1[hl] += cfr[mt][nt][0] * a0 + cfr[mt][nt][1] * a1;
                    p2[hl] += cfr[mt][nt][2] * a0 + cfr[mt][nt][3] * a1;
                }
#pragma unroll
                for (int hl = 0; hl < 2; hl++) {
                    p1[hl] += __shfl_xor_sync(0xffffffffu, p1[hl], 1);
                    p1[hl] += __shfl_xor_sync(0xffffffffu, p1[hl], 2);
                    p2[hl] += __shfl_xor_sync(0xffffffffu, p2[hl], 1);
                    p2[hl] += __shfl_xor_sync(0xffffffffu, p2[hl], 2);
                }
                if (j == 0) {
                    int h0 = warp_n * 2;
                    if (r1 < Mrows) {
                        eo[(size_t)r1 * NH + h0]     = p1[0];
                        eo[(size_t)r1 * NH + h0 + 1] = p1[1];
                    }
                    if (r2 < Mrows) {
                        eo[(size_t)r2 * NH + h0]     = p2[0];
                        eo[(size_t)r2 * NH + h0 + 1] = p2[1];
                    }
                }
            }
        }
    } else {
        if (tid < 128) redbuf[tid] = 0.f;
        __syncthreads();
#pragma unroll
        for (int mt = 0; mt < 4; mt++) {
            float p1 = 0.f, p2 = 0.f;
#pragma unroll
            for (int nt = 0; nt < 4; nt++) {
                int c = warp_n * 32 + nt * 8 + j * 2;
                float b0 = bias[c], b1 = bias[c + 1];
                float w0 = w2[c], w1 = w2[c + 1];
                p1 += tanhf(cfr[mt][nt][0] + b0) * w0 + tanhf(cfr[mt][nt][1] + b1) * w1;
                p2 += tanhf(cfr[mt][nt][2] + b0) * w0 + tanhf(cfr[mt][nt][3] + b1) * w1;
            }
            p1 += __shfl_xor_sync(0xffffffffu, p1, 1);
            p1 += __shfl_xor_sync(0xffffffffu, p1, 2);
            p2 += __shfl_xor_sync(0xffffffffu, p2, 1);
            p2 += __shfl_xor_sync(0xffffffffu, p2, 2);
            if (j == 0) {
                atomicAdd(&redbuf[warp_m * 64 + mt * 16 + g], p1);
                atomicAdd(&redbuf[warp_m * 64 + mt * 16 + g + 8], p2);
            }
        }
        __syncthreads();
        if (tid < 128) {
            int r = rowBase + tid;
            if (r < Mrows) wout[r] = redbuf[tid];
        }
    }
}

// ---------------- Vdst[m][h][k] = sum_d Wdst[m][k][h*16+d] * ar[m][h][d] ----
__global__ void vdst_kernel(const float* __restrict__ Wdst, const float* __restrict__ ar,
                            float* __restrict__ vd)
{
    int t = blockIdx.x * blockDim.x + threadIdx.x;
    if (t >= MM * NH * HID) return;
    int m = t / (NH * HID);
    int r = t - m * (NH * HID);
    int h = r / HID;
    int k = r - h * HID;
    const float* W = Wdst + ((size_t)m * HID + k) * HID + h * 16;
    const float* a = ar + (m * NH + h) * 16;
    float s = 0.f;
#pragma unroll
    for (int d = 0; d < 16; d++) s += W[d] * a[d];
    vd[(m * NH + h) * HID + k] = s;
}

// ---------------- er[m][n][h] = h_[n,:] . Vdst[m][h][:] (one warp per node) -
__global__ void er_kernel(const float* __restrict__ hfeat, const float* __restrict__ vd,
                          float* __restrict__ er)
{
    __shared__ float sV[MM * NH * HID];
    for (int i = threadIdx.x; i < MM * NH * HID; i += blockDim.x) sV[i] = vd[i];
    __syncthreads();
    int warp = (blockIdx.x * blockDim.x + threadIdx.x) >> 5;
    int lane = threadIdx.x & 31;
    if (warp >= NN) return;
    float4 hv = *reinterpret_cast<const float4*>(hfeat + (size_t)warp * HID + lane * 4);
#pragma unroll
    for (int m = 0; m < MM; m++) {
#pragma unroll
        for (int hh = 0; hh < NH; hh++) {
            float4 vv = *reinterpret_cast<const float4*>(&sV[(m * NH + hh) * HID + lane * 4]);
            float p = hv.x * vv.x + hv.y * vv.y + hv.z * vv.z + hv.w * vv.w;
            p += __shfl_xor_sync(0xffffffffu, p, 16);
            p += __shfl_xor_sync(0xffffffffu, p, 8);
            p += __shfl_xor_sync(0xffffffffu, p, 4);
            p += __shfl_xor_sync(0xffffffffu, p, 2);
            p += __shfl_xor_sync(0xffffffffu, p, 1);
            if (lane == 0) er[((size_t)m * NN + warp) * NH + hh] = p;
        }
    }
}

// ---------------- CSR build: count / scan / fill ----------------------------
__global__ void count_kernel(const int* __restrict__ dst, int* __restrict__ cnt)
{
    int t = blockIdx.x * blockDim.x + threadIdx.x;
    if (t >= MM * EE) return;
    int m = t / EE;
    atomicAdd(&cnt[m * NN + dst[t]], 1);
}

#define SCAN_T 1024
#define SCAN_CH ((SEGS + SCAN_T - 1) / SCAN_T)
__global__ void __launch_bounds__(SCAN_T) scan_kernel(const int* __restrict__ cnt,
                                                      int* __restrict__ off,
                                                      int* __restrict__ pos)
{
    __shared__ int sm[SCAN_T];
    int tid = threadIdx.x;
    int base = tid * SCAN_CH;
    int s = 0;
    for (int i = 0; i < SCAN_CH; i++) {
        int idx = base + i;
        if (idx < SEGS) s += cnt[idx];
    }
    sm[tid] = s;
    __syncthreads();
    for (int d = 1; d < SCAN_T; d <<= 1) {
        int v = (tid >= d) ? sm[tid - d] : 0;
        __syncthreads();
        sm[tid] += v;
        __syncthreads();
    }
    int run = sm[tid] - s;
    for (int i = 0; i < SCAN_CH; i++) {
        int idx = base + i;
        if (idx < SEGS) {
            off[idx] = run;
            pos[idx] = run;
            run += cnt[idx];
        }
    }
}

__global__ void fill_kernel(const int* __restrict__ src, const int* __restrict__ dst,
                            int* __restrict__ pos, int* __restrict__ ssrc)
{
    int t = blockIdx.x * blockDim.x + threadIdx.x;
    if (t >= MM * EE) return;
    int m = t / EE;
    int p = atomicAdd(&pos[m * NN + dst[t]], 1);
    ssrc[p] = src[t];
}

// ---------------- gather: per (m, dst) warp: softmax + weighted aggregation -
__global__ void gather_kernel(const int* __restrict__ ssrc,
                              const int* __restrict__ off, const int* __restrict__ cnt,
                              const float* __restrict__ el, const float* __restrict__ er,
                              const float* __restrict__ fs, float* __restrict__ z)
{
    int gw = (blockIdx.x * blockDim.x + threadIdx.x) >> 5;
    int lane = threadIdx.x & 31;
    if (gw >= SEGS) return;
    int m = gw / NN;
    int n = gw - m * NN;
    int beg = off[gw];
    int num = cnt[gw];
    const float* elm = el + (size_t)m * NN * NH;
    const float* fsm = fs + (size_t)m * NN * HID;

    int h8 = lane & 7;
    float er8 = er[(size_t)gw * NH + h8];
    float ssum = 0.f;
    for (int it = (lane >> 3); it < num; it += 4) {
        int s = ssrc[beg + it];
        float v = elm[s * NH + h8] + er8;
        v = v > 0.f ? v : 0.2f * v;
        ssum += __expf(v);
    }
    ssum += __shfl_xor_sync(0xffffffffu, ssum, 8);
    ssum += __shfl_xor_sync(0xffffffffu, ssum, 16);
    int h4 = lane >> 2;
    float ssum4 = __shfl_sync(0xffffffffu, ssum, h4);
    float er4   = __shfl_sync(0xffffffffu, er8, h4);
    float inv = 1.f / fmaxf(ssum4, 1e-9f);

    float4 acc = make_float4(0.f, 0.f, 0.f, 0.f);
    int s = (num > 0) ? ssrc[beg] : 0;
    for (int it = 0; it < num; ++it) {
        int snext = (it + 1 < num) ? ssrc[beg + it + 1] : 0;
        float v = elm[s * NH + h4] + er4;
        float4 f = *reinterpret_cast<const float4*>(fsm + (size_t)s * HID + lane * 4);
        v = v > 0.f ? v : 0.2f * v;
        float a = __expf(v) * inv;
        acc.x += f.x * a; acc.y += f.y * a; acc.z += f.z * a; acc.w += f.w * a;
        s = snext;
    }
    *reinterpret_cast<float4*>(z + ((size_t)n * MM + m) * HID + lane * 4) = acc;
}

// ---------------- final: beta softmax over w, elu(z) fuse, output GEMV ------
__global__ void final_kernel(const float* __restrict__ w, const float* __restrict__ z,
                             const float* __restrict__ Wout, const float* __restrict__ bout,
                             float* __restrict__ out)
{
    __shared__ float sW[HID * OUTD];
    for (int i = threadIdx.x; i < HID * OUTD; i += blockDim.x) sW[i] = Wout[i];
    __syncthreads();
    int warp = (blockIdx.x * blockDim.x + threadIdx.x) >> 5;
    int lane = threadIdx.x & 31;
    if (warp >= NN) return;
    float w0 = w[warp * 3 + 0], w1 = w[warp * 3 + 1], w2v = w[warp * 3 + 2];
    float mx = fmaxf(w0, fmaxf(w1, w2v));
    float e0 = __expf(w0 - mx), e1 = __expf(w1 - mx), e2 = __expf(w2v - mx);
    float inv = 1.f / (e0 + e1 + e2);
    float b0 = e0 * inv, b1 = e1 * inv, b2 = e2 * inv;
    const float* zr = z + (size_t)warp * (MM * HID);
    float4 z0 = *reinterpret_cast<const float4*>(zr + lane * 4);
    float4 z1 = *reinterpret_cast<const float4*>(zr + HID + lane * 4);
    float4 z2 = *reinterpret_cast<const float4*>(zr + 2 * HID + lane * 4);
    float f[4];
    f[0] = b0 * elu1(z0.x) + b1 * elu1(z1.x) + b2 * elu1(z2.x);
    f[1] = b0 * elu1(z0.y) + b1 * elu1(z1.y) + b2 * elu1(z2.y);
    f[2] = b0 * elu1(z0.z) + b1 * elu1(z1.z) + b2 * elu1(z2.z);
    f[3] = b0 * elu1(z0.w) + b1 * elu1(z1.w) + b2 * elu1(z2.w);
    float po[OUTD];
#pragma unroll
    for (int o = 0; o < OUTD; o++) {
        po[o] = 0.f;
#pragma unroll
        for (int j = 0; j < 4; j++)
            po[o] += f[j] * sW[(lane * 4 + j) * OUTD + o];
    }
#pragma unroll
    for (int off = 16; off; off >>= 1)
#pragma unroll
        for (int o = 0; o < OUTD; o++)
            po[o] += __shfl_down_sync(0xffffffffu, po[o], off);
    if (lane == 0)
#pragma unroll
        for (int o = 0; o < OUTD; o++)
            out[(size_t)warp * OUTD + o] = po[o] + bout[o];
}

// ---------------- launch ----------------------------------------------------
extern "C" void kernel_launch(void* const* d_in, const int* in_sizes, int n_in,
                              void* d_out, int out_size)
{
    const float* features = (const float*)d_in[0];
    const float* W_fc     = (const float*)d_in[1];
    const float* b_fc     = (const float*)d_in[2];
    const float* W_src    = (const float*)d_in[3];
    const float* W_dst    = (const float*)d_in[4];
    const float* attn_l   = (const float*)d_in[5];
    const float* attn_r   = (const float*)d_in[6];
    const float* W_sem1   = (const float*)d_in[7];
    const float* b_sem1   = (const float*)d_in[8];
    const float* w_sem2   = (const float*)d_in[9];
    const float* W_out    = (const float*)d_in[10];
    const float* b_out    = (const float*)d_in[11];
    const int*   src_idx  = (const int*)d_in[12];
    const int*   dst_idx  = (const int*)d_in[13];
    float* out = (float*)d_out;

    float *h, *fs, *el, *er, *vd, *z, *w;
    int *cnt, *off, *pos, *ssrc;
    __nv_bfloat16 *bfc, *bpr, *bsm;
    cudaGetSymbolAddress((void**)&h,   d_h);
    cudaGetSymbolAddress((void**)&fs,  d_fs);
    cudaGetSymbolAddress((void**)&el,  d_el);
    cudaGetSymbolAddress((void**)&er,  d_er);
    cudaGetSymbolAddress((void**)&vd,  d_vd);
    cudaGetSymbolAddress((void**)&z,   d_z);
    cudaGetSymbolAddress((void**)&w,   d_w);
    cudaGetSymbolAddress((void**)&cnt, d_cnt);
    cudaGetSymbolAddress((void**)&off, d_off);
    cudaGetSymbolAddress((void**)&pos, d_pos);
    cudaGetSymbolAddress((void**)&ssrc,d_ssrc);
    cudaGetSymbolAddress((void**)&bfc, d_Bfc);
    cudaGetSymbolAddress((void**)&bpr, d_Bpr);
    cudaGetSymbolAddress((void**)&bsm, d_Bsm);

    cudaMemsetAsync(cnt, 0, SEGS * sizeof(int));

    // weight prep (tiny)
    prep_b<<<(128 * F_IN + 255) / 256, 256>>>(W_fc, bfc, F_IN);
    for (int m = 0; m < MM; m++)
        prep_b<<<(128 * HID + 255) / 256, 256>>>(W_src + (size_t)m * HID * HID,
                                                 bpr + (size_t)m * 128 * 3 * HID, HID);
    prep_b<<<(128 * HID + 255) / 256, 256>>>(W_sem1, bsm, HID);

    // CSR build (independent of GEMMs)
    count_kernel<<<(MM * EE + 255) / 256, 256>>>(dst_idx, cnt);
    scan_kernel<<<1, SCAN_T>>>(cnt, off, pos);
    fill_kernel<<<(MM * EE + 255) / 256, 256>>>(src_idx, dst_idx, pos, ssrc);

    const int MT = (NN + 127) / 128;

    // h = features @ W_fc + b_fc
    mgemm<<<dim3(MT, 1), 256>>>(features, bfc, b_fc, h,
                                nullptr, nullptr, nullptr, nullptr,
                                NN, F_IN, 0);

    // fs[m] = h @ W_src[m], fused el; er via factored Vdst
    vdst_kernel<<<(MM * NH * HID + 255) / 256, 256>>>(W_dst, attn_r, vd);
    mgemm<<<dim3(MT, MM), 256>>>(h, bpr, nullptr, fs,
                                 attn_l, el, nullptr, nullptr,
                                 NN, HID, 1);
    er_kernel<<<(NN + 7) / 8, 256>>>(h, vd, er);

    // edge softmax + aggregation, atomic-free
    gather_kernel<<<(SEGS + 7) / 8, 256>>>(ssrc, off, cnt, el, er, fs, z);

    // semantic: w = tanh(elu(z) @ W_sem1 + b_sem1) . w_sem2
    mgemm<<<dim3((NN * MM + 127) / 128, 1), 256>>>(z, bsm, b_sem1, nullptr,
                                 nullptr, nullptr, w_sem2, w,
                                 NN * MM, HID, 2);

    final_kernel<<<(NN + 7) / 8, 256>>>(w, z, W_out, b_out, out);
}

// round 8
// speedup vs baseline: 1.9125x; 1.2089x over previous
#include <cuda_runtime.h>
#include <cuda_bf16.h>
#include <cstdint>

#define NN   50000
#define F_IN 256
#define HID  128
#define NH   8
#define EE   800000
#define MM   3
#define OUTD 8
#define SEGS (MM * NN)
#define CK   32   // K-chunk
#define ASTR 40   // padded smem row stride (halves)

// ---------------- scratch (device globals; no allocation) ----------------
__device__ float d_h [NN * HID];
__device__ float d_fs[(size_t)MM * NN * HID];
__device__ float d_el[(size_t)MM * NN * NH];
__device__ float d_er[(size_t)MM * NN * NH];
__device__ float d_vd[MM * NH * HID];
__device__ float d_z [(size_t)NN * MM * HID];
__device__ float d_w [NN * MM];
__device__ int   d_cnt [SEGS];
__device__ int   d_off [SEGS];
__device__ int   d_pos [SEGS];
__device__ int   d_ssrc[MM * EE];
// B' transposed weights, [128][2K]: [n][0..K)=hi, [n][K..2K)=lo
__device__ __nv_bfloat16 d_Bfc[128 * 2 * F_IN];
__device__ __nv_bfloat16 d_Bpr[MM * 128 * 2 * HID];
__device__ __nv_bfloat16 d_Bsm[128 * 2 * HID];

__device__ __forceinline__ float elu1(float v)
{
    return v > 0.f ? v : (__expf(v) - 1.f);
}

__device__ __forceinline__ uint32_t smem_u32(const void* p) {
    uint32_t a;
    asm("{ .reg .u64 t; cvta.to.shared.u64 t, %1; cvt.u32.u64 %0, t; }"
        : "=r"(a) : "l"(p));
    return a;
}

// ---------------- weight prep: B'[n] = [hi(0..K) | lo(K..2K)] ---------------
__global__ void prep_b(const float* __restrict__ W, __nv_bfloat16* __restrict__ Bp, int K)
{
    int t = blockIdx.x * blockDim.x + threadIdx.x;
    if (t >= 128 * K) return;
    int k = t >> 7;
    int n = t & 127;
    float v = W[(size_t)k * 128 + n];
    __nv_bfloat16 h = __float2bfloat16(v);
    __nv_bfloat16 l = __float2bfloat16(v - __bfloat162float(h));
    size_t base = (size_t)n * 2 * K;
    Bp[base + k]     = h;
    Bp[base + K + k] = l;
}

// ---------------- tensor-core GEMM via mma.sync, bf16 hi/lo split -----------
// D = Ah@Bh + Ah@Bl + Al@Bh  (fp32 accum); tile 128x128, 8 warps (2x4)
// mode 0: C = A@W + bias     mode 1 (grid.y=m): C = A@W ; el head-dots fused
// mode 2: A'=elu(A); wout = tanh(A'@W + bias) . w2  (no C store)
__global__ void __launch_bounds__(256) mgemm(
    const float* __restrict__ A, const __nv_bfloat16* __restrict__ Bp,
    const float* __restrict__ bias, float* __restrict__ Cb,
    const float* __restrict__ att, float* __restrict__ elb,
    const float* __restrict__ w2, float* __restrict__ wout,
    int Mrows, int K, int mode)
{
    __shared__ __nv_bfloat16 Ah[128 * ASTR];
    __shared__ __nv_bfloat16 Al[128 * ASTR];
    __shared__ __nv_bfloat16 Bh[128 * ASTR];
    __shared__ __nv_bfloat16 Bl[128 * ASTR];
    __shared__ float redbuf[128];

    const int tid = threadIdx.x;
    const int lane = tid & 31;
    const int wid = tid >> 5;
    const int warp_m = wid >> 2;      // 0..1 -> rows warp_m*64
    const int warp_n = wid & 3;       // 0..3 -> cols warp_n*32
    const int rowBase = blockIdx.x * 128;

    const __nv_bfloat16* B = Bp;
    float* C = Cb; const float* av = att; float* eo = elb;
    if (mode == 1) {
        int m = blockIdx.y;
        B  += (size_t)m * 128 * 2 * K;
        C  += (size_t)m * NN * HID;
        av += (size_t)m * HID;
        eo += (size_t)m * NN * NH;
    }

    float cfr[4][4][4];
#pragma unroll
    for (int mt = 0; mt < 4; mt++)
#pragma unroll
        for (int nt = 0; nt < 4; nt++)
#pragma unroll
            for (int q = 0; q < 4; q++) cfr[mt][nt][q] = 0.f;

    // loader mapping: row = tid>>1, 16-wide half-chunk = (tid&1)*16
    const int lrow = tid >> 1;
    const int lcol = (tid & 1) * 16;
    const bool aok = (rowBase + lrow) < Mrows;
    const float* Arow = A + (size_t)(rowBase + lrow) * K;
    const __nv_bfloat16* Bh_row = B + (size_t)lrow * 2 * K;
    const __nv_bfloat16* Bl_row = Bh_row + K;

    const uint32_t ahb = smem_u32(Ah);
    const uint32_t alb = smem_u32(Al);
    const uint32_t bhb = smem_u32(Bh);
    const uint32_t blb = smem_u32(Bl);

    for (int kc = 0; kc < K; kc += CK) {
        // ---- load A chunk fp32 -> hi/lo bf16 ----
        {
            uint32_t* dh = reinterpret_cast<uint32_t*>(&Ah[lrow * ASTR + lcol]);
            uint32_t* dl = reinterpret_cast<uint32_t*>(&Al[lrow * ASTR + lcol]);
#pragma unroll
            for (int q = 0; q < 4; q++) {
                float4 v = aok ? *reinterpret_cast<const float4*>(Arow + kc + lcol + q * 4)
                               : make_float4(0.f, 0.f, 0.f, 0.f);
                if (mode == 2) { v.x = elu1(v.x); v.y = elu1(v.y); v.z = elu1(v.z); v.w = elu1(v.w); }
                __nv_bfloat16 h0 = __float2bfloat16(v.x);
                __nv_bfloat16 h1 = __float2bfloat16(v.y);
                __nv_bfloat16 h2 = __float2bfloat16(v.z);
                __nv_bfloat16 h3 = __float2bfloat16(v.w);
                __nv_bfloat16 l0 = __float2bfloat16(v.x - __bfloat162float(h0));
                __nv_bfloat16 l1 = __float2bfloat16(v.y - __bfloat162float(h1));
                __nv_bfloat16 l2 = __float2bfloat16(v.z - __bfloat162float(h2));
                __nv_bfloat16 l3 = __float2bfloat16(v.w - __bfloat162float(h3));
                __nv_bfloat162 hp0 = __halves2bfloat162(h0, h1);
                __nv_bfloat162 hp1 = __halves2bfloat162(h2, h3);
                __nv_bfloat162 lp0 = __halves2bfloat162(l0, l1);
                __nv_bfloat162 lp1 = __halves2bfloat162(l2, l3);
                dh[q * 2]     = *reinterpret_cast<uint32_t*>(&hp0);
                dh[q * 2 + 1] = *reinterpret_cast<uint32_t*>(&hp1);
                dl[q * 2]     = *reinterpret_cast<uint32_t*>(&lp0);
                dl[q * 2 + 1] = *reinterpret_cast<uint32_t*>(&lp1);
            }
        }
        // ---- load B hi/lo chunks (pre-split, straight copy) ----
        {
            const uint4* gh = reinterpret_cast<const uint4*>(Bh_row + kc + lcol);
            const uint4* gl = reinterpret_cast<const uint4*>(Bl_row + kc + lcol);
            uint4* dh = reinterpret_cast<uint4*>(&Bh[lrow * ASTR + lcol]);
            uint4* dl = reinterpret_cast<uint4*>(&Bl[lrow * ASTR + lcol]);
            dh[0] = gh[0]; dh[1] = gh[1];
            dl[0] = gl[0]; dl[1] = gl[1];
        }
        __syncthreads();

        // ---- 2 k-steps of 16 ----
#pragma unroll
        for (int ks = 0; ks < 2; ks++) {
            int k0 = ks * 16;
            int ra = warp_m * 64 + (lane & 15);
            int ka = k0 + (lane >> 4) * 8;
            int nb = warp_n * 32 + (lane & 7);
            int kb = k0 + ((lane >> 3) & 1) * 8;

            uint32_t ah[4][4], bh[4][2], bl[4][2];
#pragma unroll
            for (int mt = 0; mt < 4; mt++) {
                uint32_t addr = ahb + (uint32_t)((ra + mt * 16) * ASTR + ka) * 2u;
                asm volatile("ldmatrix.sync.aligned.m8n8.x4.shared.b16 {%0,%1,%2,%3}, [%4];"
                             : "=r"(ah[mt][0]), "=r"(ah[mt][1]), "=r"(ah[mt][2]), "=r"(ah[mt][3])
                             : "r"(addr));
            }
#pragma unroll
            for (int nt = 0; nt < 4; nt++) {
                uint32_t addr = bhb + (uint32_t)((nb + nt * 8) * ASTR + kb) * 2u;
                asm volatile("ldmatrix.sync.aligned.m8n8.x2.shared.b16 {%0,%1}, [%2];"
                             : "=r"(bh[nt][0]), "=r"(bh[nt][1]) : "r"(addr));
                uint32_t addr2 = blb + (uint32_t)((nb + nt * 8) * ASTR + kb) * 2u;
                asm volatile("ldmatrix.sync.aligned.m8n8.x2.shared.b16 {%0,%1}, [%2];"
                             : "=r"(bl[nt][0]), "=r"(bl[nt][1]) : "r"(addr2));
            }
#pragma unroll
            for (int mt = 0; mt < 4; mt++)
#pragma unroll
                for (int nt = 0; nt < 4; nt++) {
                    asm volatile(
                        "mma.sync.aligned.m16n8k16.row.col.f32.bf16.bf16.f32 "
                        "{%0,%1,%2,%3}, {%4,%5,%6,%7}, {%8,%9}, {%0,%1,%2,%3};"
                        : "+f"(cfr[mt][nt][0]), "+f"(cfr[mt][nt][1]),
                          "+f"(cfr[mt][nt][2]), "+f"(cfr[mt][nt][3])
                        : "r"(ah[mt][0]), "r"(ah[mt][1]), "r"(ah[mt][2]), "r"(ah[mt][3]),
                          "r"(bh[nt][0]), "r"(bh[nt][1]));
                    asm volatile(
                        "mma.sync.aligned.m16n8k16.row.col.f32.bf16.bf16.f32 "
                        "{%0,%1,%2,%3}, {%4,%5,%6,%7}, {%8,%9}, {%0,%1,%2,%3};"
                        : "+f"(cfr[mt][nt][0]), "+f"(cfr[mt][nt][1]),
                          "+f"(cfr[mt][nt][2]), "+f"(cfr[mt][nt][3])
                        : "r"(ah[mt][0]), "r"(ah[mt][1]), "r"(ah[mt][2]), "r"(ah[mt][3]),
                          "r"(bl[nt][0]), "r"(bl[nt][1]));
                }
            // A_lo frags after hi frags retire (register pressure)
            uint32_t al4[4][4];
#pragma unroll
            for (int mt = 0; mt < 4; mt++) {
                uint32_t addr = alb + (uint32_t)((ra + mt * 16) * ASTR + ka) * 2u;
                asm volatile("ldmatrix.sync.aligned.m8n8.x4.shared.b16 {%0,%1,%2,%3}, [%4];"
                             : "=r"(al4[mt][0]), "=r"(al4[mt][1]), "=r"(al4[mt][2]), "=r"(al4[mt][3])
                             : "r"(addr));
            }
#pragma unroll
            for (int mt = 0; mt < 4; mt++)
#pragma unroll
                for (int nt = 0; nt < 4; nt++) {
                    asm volatile(
                        "mma.sync.aligned.m16n8k16.row.col.f32.bf16.bf16.f32 "
                        "{%0,%1,%2,%3}, {%4,%5,%6,%7}, {%8,%9}, {%0,%1,%2,%3};"
                        : "+f"(cfr[mt][nt][0]), "+f"(cfr[mt][nt][1]),
                          "+f"(cfr[mt][nt][2]), "+f"(cfr[mt][nt][3])
                        : "r"(al4[mt][0]), "r"(al4[mt][1]), "r"(al4[mt][2]), "r"(al4[mt][3]),
                          "r"(bh[nt][0]), "r"(bh[nt][1]));
                }
        }
        __syncthreads();
    }

    // ---- epilogues ----
    const int g = lane >> 2, j = lane & 3;

    if (mode == 0 || mode == 1) {
#pragma unroll
        for (int mt = 0; mt < 4; mt++) {
            int r1 = rowBase + warp_m * 64 + mt * 16 + g;
            int r2 = r1 + 8;
#pragma unroll
            for (int nt = 0; nt < 4; nt++) {
                int c = warp_n * 32 + nt * 8 + j * 2;
                float b0 = 0.f, b1 = 0.f;
                if (mode == 0) { b0 = bias[c]; b1 = bias[c + 1]; }
                if (r1 < Mrows)
                    *reinterpret_cast<float2*>(C + (size_t)r1 * HID + c) =
                        make_float2(cfr[mt][nt][0] + b0, cfr[mt][nt][1] + b1);
                if (r2 < Mrows)
                    *reinterpret_cast<float2*>(C + (size_t)r2 * HID + c) =
                        make_float2(cfr[mt][nt][2] + b0, cfr[mt][nt][3] + b1);
            }
            if (mode == 1) {
                float p1[2] = {0.f, 0.f}, p2[2] = {0.f, 0.f};
#pragma unroll
                for (int nt = 0; nt < 4; nt++) {
                    int hl = nt >> 1;
                    int c = warp_n * 32 + nt * 8 + j * 2;
                    float a0 = av[c], a1 = av[c + 1];
                    p1[hl] += cfr[mt][nt][0] * a0 + cfr[mt][nt][1] * a1;
                    p2[hl] += cfr[mt][nt][2] * a0 + cfr[mt][nt][3] * a1;
                }
#pragma unroll
                for (int hl = 0; hl < 2; hl++) {
                    p1[hl] += __shfl_xor_sync(0xffffffffu, p1[hl], 1);
                    p1[hl] += __shfl_xor_sync(0xffffffffu, p1[hl], 2);
                    p2[hl] += __shfl_xor_sync(0xffffffffu, p2[hl], 1);
                    p2[hl] += __shfl_xor_sync(0xffffffffu, p2[hl], 2);
                }
                if (j == 0) {
                    int h0 = warp_n * 2;
                    if (r1 < Mrows) {
                        eo[(size_t)r1 * NH + h0]     = p1[0];
                        eo[(size_t)r1 * NH + h0 + 1] = p1[1];
                    }
                    if (r2 < Mrows) {
                        eo[(size_t)r2 * NH + h0]     = p2[0];
                        eo[(size_t)r2 * NH + h0 + 1] = p2[1];
                    }
                }
            }
        }
    } else {
        if (tid < 128) redbuf[tid] = 0.f;
        __syncthreads();
#pragma unroll
        for (int mt = 0; mt < 4; mt++) {
            float p1 = 0.f, p2 = 0.f;
#pragma unroll
            for (int nt = 0; nt < 4; nt++) {
                int c = warp_n * 32 + nt * 8 + j * 2;
                float b0 = bias[c], b1 = bias[c + 1];
                float w0 = w2[c], w1 = w2[c + 1];
                p1 += tanhf(cfr[mt][nt][0] + b0) * w0 + tanhf(cfr[mt][nt][1] + b1) * w1;
                p2 += tanhf(cfr[mt][nt][2] + b0) * w0 + tanhf(cfr[mt][nt][3] + b1) * w1;
            }
            p1 += __shfl_xor_sync(0xffffffffu, p1, 1);
            p1 += __shfl_xor_sync(0xffffffffu, p1, 2);
            p2 += __shfl_xor_sync(0xffffffffu, p2, 1);
            p2 += __shfl_xor_sync(0xffffffffu, p2, 2);
            if (j == 0) {
                atomicAdd(&redbuf[warp_m * 64 + mt * 16 + g], p1);
                atomicAdd(&redbuf[warp_m * 64 + mt * 16 + g + 8], p2);
            }
        }
        __syncthreads();
        if (tid < 128) {
            int r = rowBase + tid;
            if (r < Mrows) wout[r] = redbuf[tid];
        }
    }
}

// ---------------- Vdst[m][h][k] = sum_d Wdst[m][k][h*16+d] * ar[m][h][d] ----
__global__ void vdst_kernel(const float* __restrict__ Wdst, const float* __restrict__ ar,
                            float* __restrict__ vd)
{
    int t = blockIdx.x * blockDim.x + threadIdx.x;
    if (t >= MM * NH * HID) return;
    int m = t / (NH * HID);
    int r = t - m * (NH * HID);
    int h = r / HID;
    int k = r - h * HID;
    const float* W = Wdst + ((size_t)m * HID + k) * HID + h * 16;
    const float* a = ar + (m * NH + h) * 16;
    float s = 0.f;
#pragma unroll
    for (int d = 0; d < 16; d++) s += W[d] * a[d];
    vd[(m * NH + h) * HID + k] = s;
}

// ---------------- er[m][n][h] = h_[n,:] . Vdst[m][h][:] (one warp per node) -
__global__ void er_kernel(const float* __restrict__ hfeat, const float* __restrict__ vd,
                          float* __restrict__ er)
{
    __shared__ float sV[MM * NH * HID];
    for (int i = threadIdx.x; i < MM * NH * HID; i += blockDim.x) sV[i] = vd[i];
    __syncthreads();
    int warp = (blockIdx.x * blockDim.x + threadIdx.x) >> 5;
    int lane = threadIdx.x & 31;
    if (warp >= NN) return;
    float4 hv = *reinterpret_cast<const float4*>(hfeat + (size_t)warp * HID + lane * 4);
#pragma unroll
    for (int m = 0; m < MM; m++) {
#pragma unroll
        for (int hh = 0; hh < NH; hh++) {
            float4 vv = *reinterpret_cast<const float4*>(&sV[(m * NH + hh) * HID + lane * 4]);
            float p = hv.x * vv.x + hv.y * vv.y + hv.z * vv.z + hv.w * vv.w;
            p += __shfl_xor_sync(0xffffffffu, p, 16);
            p += __shfl_xor_sync(0xffffffffu, p, 8);
            p += __shfl_xor_sync(0xffffffffu, p, 4);
            p += __shfl_xor_sync(0xffffffffu, p, 2);
            p += __shfl_xor_sync(0xffffffffu, p, 1);
            if (lane == 0) er[((size_t)m * NN + warp) * NH + hh] = p;
        }
    }
}

// ---------------- CSR build: count / scan / fill ----------------------------
__global__ void count_kernel(const int* __restrict__ dst, int* __restrict__ cnt)
{
    int t = blockIdx.x * blockDim.x + threadIdx.x;
    if (t >= MM * EE) return;
    int m = t / EE;
    atomicAdd(&cnt[m * NN + dst[t]], 1);
}

#define SCAN_T 1024
#define SCAN_CH ((SEGS + SCAN_T - 1) / SCAN_T)
__global__ void __launch_bounds__(SCAN_T) scan_kernel(const int* __restrict__ cnt,
                                                      int* __restrict__ off,
                                                      int* __restrict__ pos)
{
    __shared__ int sm[SCAN_T];
    int tid = threadIdx.x;
    int base = tid * SCAN_CH;
    int s = 0;
    for (int i = 0; i < SCAN_CH; i++) {
        int idx = base + i;
        if (idx < SEGS) s += cnt[idx];
    }
    sm[tid] = s;
    __syncthreads();
    for (int d = 1; d < SCAN_T; d <<= 1) {
        int v = (tid >= d) ? sm[tid - d] : 0;
        __syncthreads();
        sm[tid] += v;
        __syncthreads();
    }
    int run = sm[tid] - s;
    for (int i = 0; i < SCAN_CH; i++) {
        int idx = base + i;
        if (idx < SEGS) {
            off[idx] = run;
            pos[idx] = run;
            run += cnt[idx];
        }
    }
}

__global__ void fill_kernel(const int* __restrict__ src, const int* __restrict__ dst,
                            int* __restrict__ pos, int* __restrict__ ssrc)
{
    int t = blockIdx.x * blockDim.x + threadIdx.x;
    if (t >= MM * EE) return;
    int m = t / EE;
    int p = atomicAdd(&pos[m * NN + dst[t]], 1);
    ssrc[p] = src[t];
}

// ---------------- gather: SINGLE PASS softmax-normalized aggregation --------
// out = (sum_i e_i * fs_i) / (sum_i e_i): divide once at the end
__global__ void gather_kernel(const int* __restrict__ ssrc,
                              const int* __restrict__ off, const int* __restrict__ cnt,
                              const float* __restrict__ el, const float* __restrict__ er,
                              const float* __restrict__ fs, float* __restrict__ z)
{
    int gw = (blockIdx.x * blockDim.x + threadIdx.x) >> 5;
    int lane = threadIdx.x & 31;
    if (gw >= SEGS) return;
    int m = gw / NN;
    int n = gw - m * NN;
    int beg = off[gw];
    int num = cnt[gw];
    const float* elm = el + (size_t)m * NN * NH;
    const float* fsm = fs + (size_t)m * NN * HID;

    int h4 = lane >> 2;
    float er4 = er[(size_t)gw * NH + h4];

    float ssum = 0.f;
    float4 acc = make_float4(0.f, 0.f, 0.f, 0.f);
    int s = (num > 0) ? ssrc[beg] : 0;
    for (int it = 0; it < num; ++it) {
        int snext = (it + 1 < num) ? ssrc[beg + it + 1] : 0;
        float v = elm[s * NH + h4] + er4;
        float4 f = *reinterpret_cast<const float4*>(fsm + (size_t)s * HID + lane * 4);
        v = v > 0.f ? v : 0.2f * v;
        float e = __expf(v);
        ssum += e;
        acc.x += f.x * e; acc.y += f.y * e; acc.z += f.z * e; acc.w += f.w * e;
        s = snext;
    }
    float inv = 1.f / fmaxf(ssum, 1e-9f);
    acc.x *= inv; acc.y *= inv; acc.z *= inv; acc.w *= inv;
    *reinterpret_cast<float4*>(z + ((size_t)n * MM + m) * HID + lane * 4) = acc;
}

// ---------------- final: beta softmax over w, elu(z) fuse, output GEMV ------
__global__ void final_kernel(const float* __restrict__ w, const float* __restrict__ z,
                             const float* __restrict__ Wout, const float* __restrict__ bout,
                             float* __restrict__ out)
{
    __shared__ float sW[HID * OUTD];
    for (int i = threadIdx.x; i < HID * OUTD; i += blockDim.x) sW[i] = Wout[i];
    __syncthreads();
    int warp = (blockIdx.x * blockDim.x + threadIdx.x) >> 5;
    int lane = threadIdx.x & 31;
    if (warp >= NN) return;
    float w0 = w[warp * 3 + 0], w1 = w[warp * 3 + 1], w2v = w[warp * 3 + 2];
    float mx = fmaxf(w0, fmaxf(w1, w2v));
    float e0 = __expf(w0 - mx), e1 = __expf(w1 - mx), e2 = __expf(w2v - mx);
    float inv = 1.f / (e0 + e1 + e2);
    float b0 = e0 * inv, b1 = e1 * inv, b2 = e2 * inv;
    const float* zr = z + (size_t)warp * (MM * HID);
    float4 z0 = *reinterpret_cast<const float4*>(zr + lane * 4);
    float4 z1 = *reinterpret_cast<const float4*>(zr + HID + lane * 4);
    float4 z2 = *reinterpret_cast<const float4*>(zr + 2 * HID + lane * 4);
    float f[4];
    f[0] = b0 * elu1(z0.x) + b1 * elu1(z1.x) + b2 * elu1(z2.x);
    f[1] = b0 * elu1(z0.y) + b1 * elu1(z1.y) + b2 * elu1(z2.y);
    f[2] = b0 * elu1(z0.z) + b1 * elu1(z1.z) + b2 * elu1(z2.z);
    f[3] = b0 * elu1(z0.w) + b1 * elu1(z1.w) + b2 * elu1(z2.w);
    float po[OUTD];
#pragma unroll
    for (int o = 0; o < OUTD; o++) {
        po[o] = 0.f;
#pragma unroll
        for (int j = 0; j < 4; j++)
            po[o] += f[j] * sW[(lane * 4 + j) * OUTD + o];
    }
#pragma unroll
    for (int off = 16; off; off >>= 1)
#pragma unroll
        for (int o = 0; o < OUTD; o++)
            po[o] += __shfl_down_sync(0xffffffffu, po[o], off);
    if (lane == 0)
#pragma unroll
        for (int o = 0; o < OUTD; o++)
            out[(size_t)warp * OUTD + o] = po[o] + bout[o];
}

// ---------------- launch ----------------------------------------------------
extern "C" void kernel_launch(void* const* d_in, const int* in_sizes, int n_in,
                              void* d_out, int out_size)
{
    const float* features = (const float*)d_in[0];
    const float* W_fc     = (const float*)d_in[1];
    const float* b_fc     = (const float*)d_in[2];
    const float* W_src    = (const float*)d_in[3];
    const float* W_dst    = (const float*)d_in[4];
    const float* attn_l   = (const float*)d_in[5];
    const float* attn_r   = (const float*)d_in[6];
    const float* W_sem1   = (const float*)d_in[7];
    const float* b_sem1   = (const float*)d_in[8];
    const float* w_sem2   = (const float*)d_in[9];
    const float* W_out    = (const float*)d_in[10];
    const float* b_out    = (const float*)d_in[11];
    const int*   src_idx  = (const int*)d_in[12];
    const int*   dst_idx  = (const int*)d_in[13];
    float* out = (float*)d_out;

    float *h, *fs, *el, *er, *vd, *z, *w;
    int *cnt, *off, *pos, *ssrc;
    __nv_bfloat16 *bfc, *bpr, *bsm;
    cudaGetSymbolAddress((void**)&h,   d_h);
    cudaGetSymbolAddress((void**)&fs,  d_fs);
    cudaGetSymbolAddress((void**)&el,  d_el);
    cudaGetSymbolAddress((void**)&er,  d_er);
    cudaGetSymbolAddress((void**)&vd,  d_vd);
    cudaGetSymbolAddress((void**)&z,   d_z);
    cudaGetSymbolAddress((void**)&w,   d_w);
    cudaGetSymbolAddress((void**)&cnt, d_cnt);
    cudaGetSymbolAddress((void**)&off, d_off);
    cudaGetSymbolAddress((void**)&pos, d_pos);
    cudaGetSymbolAddress((void**)&ssrc,d_ssrc);
    cudaGetSymbolAddress((void**)&bfc, d_Bfc);
    cudaGetSymbolAddress((void**)&bpr, d_Bpr);
    cudaGetSymbolAddress((void**)&bsm, d_Bsm);

    cudaMemsetAsync(cnt, 0, SEGS * sizeof(int));

    // weight prep (tiny)
    prep_b<<<(128 * F_IN + 255) / 256, 256>>>(W_fc, bfc, F_IN);
    for (int m = 0; m < MM; m++)
        prep_b<<<(128 * HID + 255) / 256, 256>>>(W_src + (size_t)m * HID * HID,
                                                 bpr + (size_t)m * 128 * 2 * HID, HID);
    prep_b<<<(128 * HID + 255) / 256, 256>>>(W_sem1, bsm, HID);

    // CSR build (independent of GEMMs)
    count_kernel<<<(MM * EE + 255) / 256, 256>>>(dst_idx, cnt);
    scan_kernel<<<1, SCAN_T>>>(cnt, off, pos);
    fill_kernel<<<(MM * EE + 255) / 256, 256>>>(src_idx, dst_idx, pos, ssrc);

    const int MT = (NN + 127) / 128;

    // h = features @ W_fc + b_fc
    mgemm<<<dim3(MT, 1), 256>>>(features, bfc, b_fc, h,
                                nullptr, nullptr, nullptr, nullptr,
                                NN, F_IN, 0);

    // fs[m] = h @ W_src[m], fused el; er via factored Vdst
    vdst_kernel<<<(MM * NH * HID + 255) / 256, 256>>>(W_dst, attn_r, vd);
    mgemm<<<dim3(MT, MM), 256>>>(h, bpr, nullptr, fs,
                                 attn_l, el, nullptr, nullptr,
                                 NN, HID, 1);
    er_kernel<<<(NN + 7) / 8, 256>>>(h, vd, er);

    // edge softmax + aggregation, single pass, atomic-free
    gather_kernel<<<(SEGS + 7) / 8, 256>>>(ssrc, off, cnt, el, er, fs, z);

    // semantic: w = tanh(elu(z) @ W_sem1 + b_sem1) . w_sem2
    mgemm<<<dim3((NN * MM + 127) / 128, 1), 256>>>(z, bsm, b_sem1, nullptr,
                                 nullptr, nullptr, w_sem2, w,
                                 NN * MM, HID, 2);

    final_kernel<<<(NN + 7) / 8, 256>>>(w, z, W_out, b_out, out);
}